// round 4
// baseline (speedup 1.0000x reference)
#include <cuda_runtime.h>
#include <math.h>

#define NPART 32
#define NT    8192                  // table nodes; NT-1 cubic intervals
#define T0F   (-2.99573227355399099343f)   // logf(0.05)
#define T1F   ( 3.46573590279972654709f)   // logf(32)
#define HTF   ((T1F - T0F) / (float)(NT - 1))
#define INVHT ((float)(NT - 1) / (T1F - T0F))

__device__ float4 g_coef[NT];       // per-interval poly coeffs in s: v = c0+s(c1+s(c2+s*c3))

// ---------------------------------------------------------------------------
// Builder: one warp per interval, evaluates v and dv/dt at both endpoints
// (lanes split the 64 hidden units), converts Hermite -> monomial coeffs.
// ---------------------------------------------------------------------------
__global__ void __launch_bounds__(256)
build_table(const float* __restrict__ gW1, const float* __restrict__ gb1,
            const float* __restrict__ gW2, const float* __restrict__ gb2,
            const float* __restrict__ gW3, const float* __restrict__ gb3)
{
    __shared__ float sW2T[64 * 64];       // [jj][k]
    __shared__ float sW1[192], sb1[64], sb2[64], sW3[64];
    __shared__ float sh[8][2][64], sth[8][2][64];   // [warp][endpoint][k]
    const int tid = threadIdx.x, lane = tid & 31, wrp = tid >> 5;

    for (int idx = tid; idx < 4096; idx += 256) {
        int k = idx >> 6, jj = idx & 63;           // gW2 is [k][jj]
        sW2T[jj * 64 + k] = gW2[idx];
    }
    for (int k = tid; k < 192; k += 256) sW1[k] = gW1[k];
    for (int k = tid; k < 64; k += 256) {
        sb1[k] = gb1[k]; sb2[k] = gb2[k]; sW3[k] = gW3[k];
    }
    __syncthreads();

    const int m = blockIdx.x * 8 + wrp;           // interval index
    if (m >= NT - 1) return;

    float dnode[2];
    // layer-1 activations + d-derivatives for both endpoints, 2 k's per lane
    #pragma unroll
    for (int e = 0; e < 2; e++) {
        float t = T0F + (m + e) * HTF;
        float d = expf(t);
        dnode[e] = d;
        float inv = 1.0f / d, inv2 = inv * inv;
        float e2 = -inv2, e3 = -2.0f * inv2 * inv;
        #pragma unroll
        for (int q = 0; q < 2; q++) {
            int k = lane + q * 32;
            float w0 = sW1[k], w1 = sW1[64 + k], w2 = sW1[128 + k];
            float z  = sb1[k] + d * w0 + inv * w1 + inv2 * w2;
            float hk = tanhf(z);
            sh[wrp][e][k]  = hk;
            sth[wrp][e][k] = (1.0f - hk * hk) * (w0 + e2 * w1 + e3 * w2);
        }
    }
    __syncwarp();

    float vp[2] = {0.f, 0.f}, gp[2] = {0.f, 0.f};
    #pragma unroll
    for (int e = 0; e < 2; e++) {
        const float* hh = sh[wrp][e];
        const float* tt = sth[wrp][e];
        #pragma unroll
        for (int q = 0; q < 2; q++) {
            int jj = lane + q * 32;
            const float4* row = (const float4*)(&sW2T[jj * 64]);
            float a0 = 0.f, a1 = 0.f, b0 = 0.f, b1 = 0.f;
            #pragma unroll
            for (int r = 0; r < 16; r++) {
                float4 w = row[r];
                a0 = fmaf(hh[4 * r + 0], w.x, a0);
                a1 = fmaf(hh[4 * r + 1], w.y, a1);
                a0 = fmaf(hh[4 * r + 2], w.z, a0);
                a1 = fmaf(hh[4 * r + 3], w.w, a1);
                b0 = fmaf(tt[4 * r + 0], w.x, b0);
                b1 = fmaf(tt[4 * r + 1], w.y, b1);
                b0 = fmaf(tt[4 * r + 2], w.z, b0);
                b1 = fmaf(tt[4 * r + 3], w.w, b1);
            }
            float z2 = sb2[jj] + a0 + a1;
            float t2 = tanhf(z2);
            float w3 = sW3[jj];
            vp[e] = fmaf(t2, w3, vp[e]);
            gp[e] = fmaf(w3 * (1.0f - t2 * t2), b0 + b1, gp[e]);
        }
    }
    #pragma unroll
    for (int off = 16; off; off >>= 1) {
        vp[0] += __shfl_xor_sync(0xffffffffu, vp[0], off);
        vp[1] += __shfl_xor_sync(0xffffffffu, vp[1], off);
        gp[0] += __shfl_xor_sync(0xffffffffu, gp[0], off);
        gp[1] += __shfl_xor_sync(0xffffffffu, gp[1], off);
    }
    if (lane == 0) {
        float b3v = gb3[0];
        float p0 = vp[0] + b3v, p1 = vp[1] + b3v;
        float m0 = gp[0] * dnode[0] * HTF;   // dv/ds at s=0
        float m1 = gp[1] * dnode[1] * HTF;   // dv/ds at s=1
        float c0 = p0;
        float c1 = m0;
        float c2 = 3.f * (p1 - p0) - 2.f * m0 - m1;
        float c3 = 2.f * (p0 - p1) + m0 + m1;
        g_coef[m] = make_float4(c0, c1, c2, c3);
    }
}

// ---------------------------------------------------------------------------
// Forces: one warp per batch, lane = particle. No smem, no atomics, no syncs.
// ---------------------------------------------------------------------------
__global__ void __launch_bounds__(256)
forces_kernel(const float* __restrict__ gpos, float* __restrict__ out, int B)
{
    const int lane = threadIdx.x & 31;
    const int b = blockIdx.x * 8 + (threadIdx.x >> 5);
    if (b >= B) return;

    const float px = gpos[b * 96 + lane * 3 + 0];
    const float py = gpos[b * 96 + lane * 3 + 1];
    const float pz = gpos[b * 96 + lane * 3 + 2];

    float fx = 0.f, fy = 0.f, fz = 0.f, vloc = 0.f;

    #pragma unroll 8
    for (int j = 0; j < NPART; j++) {
        float sx = __shfl_sync(0xffffffffu, px, j);
        float sy = __shfl_sync(0xffffffffu, py, j);
        float sz = __shfl_sync(0xffffffffu, pz, j);
        float rx = px - sx, ry = py - sy, rz = pz - sz;
        float d2 = rx * rx + ry * ry + rz * rz;
        float dist = sqrtf(d2);

        float t = __logf(dist);                       // -inf when j==i, safe
        float u = (t - T0F) * INVHT;
        u = fminf(fmaxf(u, 0.0f), (float)NT - 1.001f);
        int   i0 = (int)u;
        float s  = u - (float)i0;
        float4 c = __ldg(&g_coef[i0]);

        float v  = fmaf(fmaf(fmaf(c.w, s, c.z), s, c.y), s, c.x);
        float dp = fmaf(fmaf(3.f * c.w, s, 2.f * c.z), s, c.y);   // dv/ds
        float coef = dp * INVHT * __fdividef(1.0f, d2);           // dv/dd / dist

        bool self = (j == lane);
        bool act  = !self && (dist > 0.05f);
        coef = act ? coef : 0.0f;     // clipped/self: zero force
        v    = self ? 0.0f : v;       // clipped keeps v(0.05) (u clamps to 0)

        fx = fmaf(-coef, rx, fx);
        fy = fmaf(-coef, ry, fy);
        fz = fmaf(-coef, rz, fz);
        vloc += v;
    }

    out[b * 96 + lane * 3 + 0] = fx;
    out[b * 96 + lane * 3 + 1] = fy;
    out[b * 96 + lane * 3 + 2] = fz;

    #pragma unroll
    for (int off = 16; off; off >>= 1)
        vloc += __shfl_xor_sync(0xffffffffu, vloc, off);
    if (lane == 0)
        out[(long long)B * 96 + b] = 0.5f * vloc;
}

extern "C" void kernel_launch(void* const* d_in, const int* in_sizes, int n_in,
                              void* d_out, int out_size)
{
    const float* pos = (const float*)d_in[0];
    const float* W1  = (const float*)d_in[1];
    const float* b1  = (const float*)d_in[2];
    const float* W2  = (const float*)d_in[3];
    const float* b2  = (const float*)d_in[4];
    const float* W3  = (const float*)d_in[5];
    const float* b3  = (const float*)d_in[6];
    float* out = (float*)d_out;
    const int B = in_sizes[0] / 96;

    build_table<<<(NT - 1 + 7) / 8, 256>>>(W1, b1, W2, b2, W3, b3);
    forces_kernel<<<(B + 7) / 8, 256>>>(pos, out, B);
}

// round 5
// speedup vs baseline: 1.9490x; 1.9490x over previous
#include <cuda_runtime.h>
#include <math.h>

#define NPART 32
#define NT    4096
#define T0F   (-2.99573227355399099343f)   // logf(0.05)
#define T1F   ( 3.46573590279972654709f)   // logf(32)
#define HTF   ((T1F - T0F) / (float)(NT - 1))
#define INVHT ((float)(NT - 1) / (T1F - T0F))
#define LN2F  (0.69314718055994530942f)

__device__ float4 g_node[NT];   // (v, v'_s, g, g'_s)  slopes pre-scaled by HTF
__device__ float4 g_coefV[NT];  // value cubic  in s
__device__ float4 g_coefG[NT];  // force-coef cubic in s; g = (dv/dd)/d

__device__ __forceinline__ float fast_tanh(float x) {
    float ax = fabsf(x);
    float e  = __expf(ax + ax);
    float t  = 1.0f - __fdividef(2.0f, e + 1.0f);
    return copysignf(t, x);
}

// ---------------------------------------------------------------------------
// Builder: one warp per node; 2nd-order forward AD w.r.t. t = log d.
// ---------------------------------------------------------------------------
__global__ void __launch_bounds__(256)
build_table(const float* __restrict__ gW1, const float* __restrict__ gb1,
            const float* __restrict__ gW2, const float* __restrict__ gb2,
            const float* __restrict__ gW3, const float* __restrict__ gb3)
{
    __shared__ float sW2T[64 * 64];                    // [jj][k]
    __shared__ float sW1[192], sb1[64], sb2[64], sW3[64];
    __shared__ float4 sh[8][16], shp[8][16], shpp[8][16];   // per-warp h, h', h''
    const int tid = threadIdx.x, lane = tid & 31, wrp = tid >> 5;

    for (int idx = tid; idx < 4096; idx += 256) {
        int k = idx >> 6, jj = idx & 63;               // gW2 is [k][jj]
        sW2T[jj * 64 + k] = gW2[idx];
    }
    for (int k = tid; k < 192; k += 256) sW1[k] = gW1[k];
    for (int k = tid; k < 64; k += 256) {
        sb1[k] = gb1[k]; sb2[k] = gb2[k]; sW3[k] = gW3[k];
    }
    __syncthreads();

    const int node = blockIdx.x * 8 + wrp;
    if (node >= NT) return;

    const float t  = T0F + node * HTF;
    const float d  = expf(t);
    const float f1 = d, f2 = 1.0f / d, f3 = f2 * f2;

    // phase A: layer 1 with (value, d/dt, d2/dt2); lane owns k and k+32
    float* shs   = (float*)sh[wrp];
    float* shps  = (float*)shp[wrp];
    float* shpps = (float*)shpp[wrp];
    #pragma unroll
    for (int q = 0; q < 2; q++) {
        int k = lane + q * 32;
        float w0 = sW1[k], w1 = sW1[64 + k], w2 = sW1[128 + k];
        float z   = sb1[k] + w0 * f1 + w1 * f2 + w2 * f3;
        float zp  = w0 * f1 - w1 * f2 - 2.0f * w2 * f3;
        float zpp = w0 * f1 + w1 * f2 + 4.0f * w2 * f3;
        float h   = fast_tanh(z);
        float sech2 = 1.0f - h * h;
        shs[k]   = h;
        shps[k]  = sech2 * zp;
        shpps[k] = sech2 * (zpp - 2.0f * h * zp * zp);
    }
    __syncwarp();

    // phase B: lane owns rows jj = lane, lane+32
    float va = 0.f, vpa = 0.f, vppa = 0.f;
    #pragma unroll
    for (int q = 0; q < 2; q++) {
        int jj = lane + q * 32;
        const float4* wrow = (const float4*)(&sW2T[jj * 64]);
        float z2 = sb2[jj], z2p = 0.f, z2pp = 0.f;
        #pragma unroll
        for (int r = 0; r < 16; r++) {
            int rr = (r + lane) & 15;                  // rotate: <=2-way conflict
            float4 w  = wrow[rr];
            float4 h4 = sh[wrp][rr];
            float4 p4 = shp[wrp][rr];
            float4 s4 = shpp[wrp][rr];
            z2   = fmaf(w.x, h4.x, fmaf(w.y, h4.y, fmaf(w.z, h4.z, fmaf(w.w, h4.w, z2))));
            z2p  = fmaf(w.x, p4.x, fmaf(w.y, p4.y, fmaf(w.z, p4.z, fmaf(w.w, p4.w, z2p))));
            z2pp = fmaf(w.x, s4.x, fmaf(w.y, s4.y, fmaf(w.z, s4.z, fmaf(w.w, s4.w, z2pp))));
        }
        float t2 = fast_tanh(z2);
        float sc = 1.0f - t2 * t2;
        float w3 = sW3[jj];
        va   = fmaf(w3, t2, va);
        vpa  = fmaf(w3 * sc, z2p, vpa);
        vppa = fmaf(w3 * sc, z2pp - 2.0f * t2 * z2p * z2p, vppa);
    }
    #pragma unroll
    for (int off = 16; off; off >>= 1) {
        va   += __shfl_xor_sync(0xffffffffu, va,   off);
        vpa  += __shfl_xor_sync(0xffffffffu, vpa,  off);
        vppa += __shfl_xor_sync(0xffffffffu, vppa, off);
    }
    if (lane == 0) {
        float v  = va + gb3[0];
        float em2t = f3;                               // e^{-2t}
        float g  = vpa * em2t;                         // (dv/dd)/d
        float gp = (vppa - 2.0f * vpa) * em2t;         // dg/dt
        g_node[node] = make_float4(v, vpa * HTF, g, gp * HTF);
    }
}

// ---------------------------------------------------------------------------
// Hermite endpoints -> monomial coefficients per interval.
// ---------------------------------------------------------------------------
__global__ void __launch_bounds__(256)
make_coefs()
{
    int i = blockIdx.x * 256 + threadIdx.x;
    if (i >= NT - 1) return;
    float4 n0 = g_node[i], n1 = g_node[i + 1];
    float dv = n1.x - n0.x;
    g_coefV[i] = make_float4(n0.x, n0.y, 3.f * dv - 2.f * n0.y - n1.y,
                             -2.f * dv + n0.y + n1.y);
    float dg = n1.z - n0.z;
    g_coefG[i] = make_float4(n0.z, n0.w, 3.f * dg - 2.f * n0.w - n1.w,
                             -2.f * dg + n0.w + n1.w);
}

// ---------------------------------------------------------------------------
// Forces: one warp per batch, lane = particle. No sqrt, no div, 1 MUFU/pair.
// ---------------------------------------------------------------------------
__global__ void __launch_bounds__(256)
forces_kernel(const float* __restrict__ gpos, float* __restrict__ out, int B)
{
    __shared__ float4 ppos[8][NPART];
    const int lane = threadIdx.x & 31;
    const int wrp  = threadIdx.x >> 5;
    const int b = blockIdx.x * 8 + wrp;
    if (b >= B) return;

    const float px = gpos[b * 96 + lane * 3 + 0];
    const float py = gpos[b * 96 + lane * 3 + 1];
    const float pz = gpos[b * 96 + lane * 3 + 2];
    ppos[wrp][lane] = make_float4(px, py, pz, 0.f);
    __syncwarp();

    // u = (0.5*ln(d2) - T0) * INVHT  via one LG2
    const float KL = 0.5f * LN2F * INVHT;
    const float C0 = -T0F * INVHT;

    float fx = 0.f, fy = 0.f, fz = 0.f, vloc = 0.f;

    #pragma unroll 8
    for (int j = 0; j < NPART; j++) {
        float4 pj = ppos[wrp][j];
        float rx = px - pj.x, ry = py - pj.y, rz = pj.z;  // placeholder fix below
        rz = pz - pj.z;
        float d2 = fmaf(rx, rx, fmaf(ry, ry, rz * rz));

        float u = fmaf(__log2f(d2), KL, C0);               // -inf when j==lane
        u = fminf(fmaxf(u, 0.0f), (float)NT - 1.001f);
        int   i0 = (int)u;
        float s  = u - (float)i0;

        float4 cv = __ldg(&g_coefV[i0]);
        float4 cg = __ldg(&g_coefG[i0]);
        float v = fmaf(fmaf(fmaf(cv.w, s, cv.z), s, cv.y), s, cv.x);
        float g = fmaf(fmaf(fmaf(cg.w, s, cg.z), s, cg.y), s, cg.x);

        bool self = (j == lane);
        bool act  = (d2 > 0.0025f) && !self;
        g = act  ? g : 0.0f;       // clipped or self: zero force
        v = self ? 0.0f : v;       // clipped keeps v at node 0 (u clamped)

        fx = fmaf(-g, rx, fx);
        fy = fmaf(-g, ry, fy);
        fz = fmaf(-g, rz, fz);
        vloc += v;
    }

    out[b * 96 + lane * 3 + 0] = fx;
    out[b * 96 + lane * 3 + 1] = fy;
    out[b * 96 + lane * 3 + 2] = fz;

    #pragma unroll
    for (int off = 16; off; off >>= 1)
        vloc += __shfl_xor_sync(0xffffffffu, vloc, off);
    if (lane == 0)
        out[(long long)B * 96 + b] = 0.5f * vloc;
}

extern "C" void kernel_launch(void* const* d_in, const int* in_sizes, int n_in,
                              void* d_out, int out_size)
{
    const float* pos = (const float*)d_in[0];
    const float* W1  = (const float*)d_in[1];
    const float* b1  = (const float*)d_in[2];
    const float* W2  = (const float*)d_in[3];
    const float* b2  = (const float*)d_in[4];
    const float* W3  = (const float*)d_in[5];
    const float* b3  = (const float*)d_in[6];
    float* out = (float*)d_out;
    const int B = in_sizes[0] / 96;

    build_table<<<(NT + 7) / 8, 256>>>(W1, b1, W2, b2, W3, b3);
    make_coefs<<<(NT + 255) / 256, 256>>>();
    forces_kernel<<<(B + 7) / 8, 256>>>(pos, out, B);
}

// round 6
// speedup vs baseline: 2.1768x; 1.1169x over previous
#include <cuda_runtime.h>
#include <math.h>

#define NPART 32
#define NT    2048
#define T0F   (-2.99573227355399099343f)   // logf(0.05)
#define T1F   ( 3.46573590279972654709f)   // logf(32)
#define HTF   ((T1F - T0F) / (float)(NT - 1))
#define INVHT ((float)(NT - 1) / (T1F - T0F))
#define LN2F  (0.69314718055994530942f)

__device__ float4 g_node[NT];        // (v, v'_s, g, g'_s), slopes pre-scaled by HTF
__device__ float4 g_coef[2 * NT];    // interval i: [2i]=value cubic, [2i+1]=force cubic

__device__ __forceinline__ float fast_tanh(float x) {
    float ax = fabsf(x);
    float e  = __expf(ax + ax);
    float t  = 1.0f - __fdividef(2.0f, e + 1.0f);
    return copysignf(t, x);
}

// ---------------------------------------------------------------------------
// Builder: one warp per node; 2nd-order forward AD w.r.t. t = log d.
// Lane owns rows jj=lane and jj=lane+32; h chunks loaded once per r-iter.
// ---------------------------------------------------------------------------
__global__ void __launch_bounds__(256)
build_table(const float* __restrict__ gW1, const float* __restrict__ gb1,
            const float* __restrict__ gW2, const float* __restrict__ gb2,
            const float* __restrict__ gW3, const float* __restrict__ gb3)
{
    __shared__ float sW2T[64 * 64];                  // [jj][k]
    __shared__ float sW1[192], sb1[64], sb2[64], sW3[64];
    __shared__ float4 sh[8][16], shp[8][16], shpp[8][16];
    const int tid = threadIdx.x, lane = tid & 31, wrp = tid >> 5;

    for (int idx = tid; idx < 4096; idx += 256) {
        int k = idx >> 6, jj = idx & 63;             // gW2 is [k][jj]
        sW2T[jj * 64 + k] = gW2[idx];
    }
    for (int k = tid; k < 192; k += 256) sW1[k] = gW1[k];
    for (int k = tid; k < 64; k += 256) {
        sb1[k] = gb1[k]; sb2[k] = gb2[k]; sW3[k] = gW3[k];
    }
    __syncthreads();

    const int node = blockIdx.x * 8 + wrp;
    if (node >= NT) return;

    const float t  = T0F + node * HTF;
    const float d  = expf(t);
    const float f1 = d, f2 = 1.0f / d, f3 = f2 * f2;

    // phase A: layer-1 (value, d/dt, d2/dt2); lane fills k=lane, k=lane+32
    float* shs   = (float*)sh[wrp];
    float* shps  = (float*)shp[wrp];
    float* shpps = (float*)shpp[wrp];
    #pragma unroll
    for (int q = 0; q < 2; q++) {
        int k = lane + q * 32;
        float w0 = sW1[k], w1 = sW1[64 + k], w2 = sW1[128 + k];
        float z   = sb1[k] + w0 * f1 + w1 * f2 + w2 * f3;
        float zp  = w0 * f1 - w1 * f2 - 2.0f * w2 * f3;
        float zpp = w0 * f1 + w1 * f2 + 4.0f * w2 * f3;
        float h   = fast_tanh(z);
        float s2  = 1.0f - h * h;
        shs[k]   = h;
        shps[k]  = s2 * zp;
        shpps[k] = s2 * (zpp - 2.0f * h * zp * zp);
    }
    __syncwarp();

    // phase B: both rows in one pass over k-chunks (rotated to spread banks)
    const float4* wra = (const float4*)(&sW2T[lane * 64]);
    const float4* wrb = (const float4*)(&sW2T[(lane + 32) * 64]);
    float za = sb2[lane],      zap = 0.f, zapp = 0.f;
    float zb = sb2[lane + 32], zbp = 0.f, zbpp = 0.f;
    #pragma unroll
    for (int r = 0; r < 16; r++) {
        int rr = (r + lane) & 15;
        float4 h4 = sh[wrp][rr];
        float4 p4 = shp[wrp][rr];
        float4 s4 = shpp[wrp][rr];
        float4 wa = wra[rr];
        float4 wb = wrb[rr];
        za   = fmaf(wa.x, h4.x, fmaf(wa.y, h4.y, fmaf(wa.z, h4.z, fmaf(wa.w, h4.w, za))));
        zap  = fmaf(wa.x, p4.x, fmaf(wa.y, p4.y, fmaf(wa.z, p4.z, fmaf(wa.w, p4.w, zap))));
        zapp = fmaf(wa.x, s4.x, fmaf(wa.y, s4.y, fmaf(wa.z, s4.z, fmaf(wa.w, s4.w, zapp))));
        zb   = fmaf(wb.x, h4.x, fmaf(wb.y, h4.y, fmaf(wb.z, h4.z, fmaf(wb.w, h4.w, zb))));
        zbp  = fmaf(wb.x, p4.x, fmaf(wb.y, p4.y, fmaf(wb.z, p4.z, fmaf(wb.w, p4.w, zbp))));
        zbpp = fmaf(wb.x, s4.x, fmaf(wb.y, s4.y, fmaf(wb.z, s4.z, fmaf(wb.w, s4.w, zbpp))));
    }

    float ta = fast_tanh(za), tb = fast_tanh(zb);
    float sa = 1.0f - ta * ta, sb = 1.0f - tb * tb;
    float w3a = sW3[lane], w3b = sW3[lane + 32];
    float va   = fmaf(w3a, ta, w3b * tb);
    float vpa  = fmaf(w3a * sa, zap, w3b * sb * zbp);
    float vppa = fmaf(w3a * sa, zapp - 2.0f * ta * zap * zap,
                      w3b * sb * (zbpp - 2.0f * tb * zbp * zbp));

    #pragma unroll
    for (int off = 16; off; off >>= 1) {
        va   += __shfl_xor_sync(0xffffffffu, va,   off);
        vpa  += __shfl_xor_sync(0xffffffffu, vpa,  off);
        vppa += __shfl_xor_sync(0xffffffffu, vppa, off);
    }
    if (lane == 0) {
        float v    = va + gb3[0];
        float em2t = f3;                            // e^{-2t}
        float g    = vpa * em2t;                    // (dv/dd)/d
        float gp   = (vppa - 2.0f * vpa) * em2t;    // dg/dt
        g_node[node] = make_float4(v, vpa * HTF, g, gp * HTF);
    }
}

// ---------------------------------------------------------------------------
// Hermite endpoints -> monomial coefficients, interleaved V/G per interval.
// ---------------------------------------------------------------------------
__global__ void __launch_bounds__(256)
make_coefs()
{
    int i = blockIdx.x * 256 + threadIdx.x;
    if (i >= NT - 1) return;
    float4 n0 = g_node[i], n1 = g_node[i + 1];
    float dv = n1.x - n0.x;
    g_coef[2 * i]     = make_float4(n0.x, n0.y, 3.f * dv - 2.f * n0.y - n1.y,
                                    -2.f * dv + n0.y + n1.y);
    float dg = n1.z - n0.z;
    g_coef[2 * i + 1] = make_float4(n0.z, n0.w, 3.f * dg - 2.f * n0.w - n1.w,
                                    -2.f * dg + n0.w + n1.w);
}

// ---------------------------------------------------------------------------
// Forces: one warp per batch, lane = particle. No sqrt, no div, 1 MUFU/pair.
// ---------------------------------------------------------------------------
__global__ void __launch_bounds__(256)
forces_kernel(const float* __restrict__ gpos, float* __restrict__ out, int B)
{
    __shared__ float4 ppos[8][NPART];
    const int lane = threadIdx.x & 31;
    const int wrp  = threadIdx.x >> 5;
    const int b = blockIdx.x * 8 + wrp;
    if (b >= B) return;

    const float px = gpos[b * 96 + lane * 3 + 0];
    const float py = gpos[b * 96 + lane * 3 + 1];
    const float pz = gpos[b * 96 + lane * 3 + 2];
    ppos[wrp][lane] = make_float4(px, py, pz, 0.f);
    __syncwarp();

    const float KL = 0.5f * LN2F * INVHT;   // u = (0.5*ln(d2) - T0) * INVHT
    const float C0 = -T0F * INVHT;

    float fx = 0.f, fy = 0.f, fz = 0.f, vloc = 0.f;

    #pragma unroll 8
    for (int j = 0; j < NPART; j++) {
        float4 pj = ppos[wrp][j];
        float rx = px - pj.x, ry = py - pj.y, rz = pz - pj.z;
        float d2 = fmaf(rx, rx, fmaf(ry, ry, rz * rz));

        float u = fmaf(__log2f(d2), KL, C0);        // -inf when j==lane
        u = fminf(fmaxf(u, 0.0f), (float)NT - 1.001f);
        int   i0 = (int)u;
        float s  = u - (float)i0;

        float4 cv = __ldg(&g_coef[2 * i0]);
        float4 cg = __ldg(&g_coef[2 * i0 + 1]);
        float v = fmaf(fmaf(fmaf(cv.w, s, cv.z), s, cv.y), s, cv.x);
        float g = fmaf(fmaf(fmaf(cg.w, s, cg.z), s, cg.y), s, cg.x);

        bool self = (j == lane);
        bool act  = (d2 > 0.0025f) && !self;
        g = act  ? g : 0.0f;       // clipped or self: zero force
        v = self ? 0.0f : v;       // clipped keeps node-0 value (u clamped)

        fx = fmaf(-g, rx, fx);
        fy = fmaf(-g, ry, fy);
        fz = fmaf(-g, rz, fz);
        vloc += v;
    }

    out[b * 96 + lane * 3 + 0] = fx;
    out[b * 96 + lane * 3 + 1] = fy;
    out[b * 96 + lane * 3 + 2] = fz;

    #pragma unroll
    for (int off = 16; off; off >>= 1)
        vloc += __shfl_xor_sync(0xffffffffu, vloc, off);
    if (lane == 0)
        out[(long long)B * 96 + b] = 0.5f * vloc;
}

extern "C" void kernel_launch(void* const* d_in, const int* in_sizes, int n_in,
                              void* d_out, int out_size)
{
    const float* pos = (const float*)d_in[0];
    const float* W1  = (const float*)d_in[1];
    const float* b1  = (const float*)d_in[2];
    const float* W2  = (const float*)d_in[3];
    const float* b2  = (const float*)d_in[4];
    const float* W3  = (const float*)d_in[5];
    const float* b3  = (const float*)d_in[6];
    float* out = (float*)d_out;
    const int B = in_sizes[0] / 96;

    build_table<<<(NT + 7) / 8, 256>>>(W1, b1, W2, b2, W3, b3);
    make_coefs<<<(NT + 255) / 256, 256>>>();
    forces_kernel<<<(B + 7) / 8, 256>>>(pos, out, B);
}

// round 7
// speedup vs baseline: 2.5061x; 1.1513x over previous
#include <cuda_runtime.h>
#include <math.h>

#define NPART 32
#define NT    1024
#define T0F   (-2.99573227355399099343f)   // logf(0.05)
#define T1F   ( 3.46573590279972654709f)   // logf(32)
#define HTF   ((T1F - T0F) / (float)(NT - 1))
#define INVHT ((float)(NT - 1) / (T1F - T0F))
#define LN2F  (0.69314718055994530942f)

__device__ float4 g_coef[2 * NT];   // interval i: [2i]=value cubic, [2i+1]=force cubic

__device__ __forceinline__ float fast_tanh(float x) {
    float ax = fabsf(x);
    float e  = __expf(ax + ax);
    float t  = 1.0f - __fdividef(2.0f, e + 1.0f);
    return copysignf(t, x);
}

// ---------------------------------------------------------------------------
// Builder: block bn computes nodes 7*bn .. 7*bn+7 (one per warp; one-node
// overlap with next block), then converts intervals 7*bn .. 7*bn+6 to
// monomial coefficients in-block. 2nd-order forward AD w.r.t. t = log d.
// ---------------------------------------------------------------------------
__global__ void __launch_bounds__(256)
build_table(const float* __restrict__ gW1, const float* __restrict__ gb1,
            const float* __restrict__ gW2, const float* __restrict__ gb2,
            const float* __restrict__ gW3, const float* __restrict__ gb3)
{
    __shared__ float sW2T[64 * 64];                  // [jj][k]
    __shared__ float sW1[192], sb1[64], sb2[64], sW3[64];
    __shared__ float4 sh[8][16], shp[8][16], shpp[8][16];
    __shared__ float4 snode[8];                      // (v, v'_s, g, g'_s)
    const int tid = threadIdx.x, lane = tid & 31, wrp = tid >> 5;

    for (int idx = tid; idx < 4096; idx += 256) {
        int k = idx >> 6, jj = idx & 63;             // gW2 is [k][jj]
        sW2T[jj * 64 + k] = gW2[idx];
    }
    for (int k = tid; k < 192; k += 256) sW1[k] = gW1[k];
    for (int k = tid; k < 64; k += 256) {
        sb1[k] = gb1[k]; sb2[k] = gb2[k]; sW3[k] = gW3[k];
    }
    __syncthreads();

    const int base = blockIdx.x * 7;
    const int node = min(base + wrp, NT - 1);

    const float t  = T0F + node * HTF;
    const float d  = expf(t);
    const float f1 = d, f2 = 1.0f / d, f3 = f2 * f2;

    // phase A: layer-1 (value, d/dt, d2/dt2); lane fills k=lane, k=lane+32
    float* shs   = (float*)sh[wrp];
    float* shps  = (float*)shp[wrp];
    float* shpps = (float*)shpp[wrp];
    #pragma unroll
    for (int q = 0; q < 2; q++) {
        int k = lane + q * 32;
        float w0 = sW1[k], w1 = sW1[64 + k], w2 = sW1[128 + k];
        float z   = sb1[k] + w0 * f1 + w1 * f2 + w2 * f3;
        float zp  = w0 * f1 - w1 * f2 - 2.0f * w2 * f3;
        float zpp = w0 * f1 + w1 * f2 + 4.0f * w2 * f3;
        float h   = fast_tanh(z);
        float s2  = 1.0f - h * h;
        shs[k]   = h;
        shps[k]  = s2 * zp;
        shpps[k] = s2 * (zpp - 2.0f * h * zp * zp);
    }
    __syncwarp();

    // phase B: lane owns rows jj=lane, lane+32; one pass over k-chunks
    const float4* wra = (const float4*)(&sW2T[lane * 64]);
    const float4* wrb = (const float4*)(&sW2T[(lane + 32) * 64]);
    float za = sb2[lane],      zap = 0.f, zapp = 0.f;
    float zb = sb2[lane + 32], zbp = 0.f, zbpp = 0.f;
    #pragma unroll
    for (int r = 0; r < 16; r++) {
        int rr = (r + lane) & 15;                    // rotate: spread banks
        float4 h4 = sh[wrp][rr];
        float4 p4 = shp[wrp][rr];
        float4 s4 = shpp[wrp][rr];
        float4 wa = wra[rr];
        float4 wb = wrb[rr];
        za   = fmaf(wa.x, h4.x, fmaf(wa.y, h4.y, fmaf(wa.z, h4.z, fmaf(wa.w, h4.w, za))));
        zap  = fmaf(wa.x, p4.x, fmaf(wa.y, p4.y, fmaf(wa.z, p4.z, fmaf(wa.w, p4.w, zap))));
        zapp = fmaf(wa.x, s4.x, fmaf(wa.y, s4.y, fmaf(wa.z, s4.z, fmaf(wa.w, s4.w, zapp))));
        zb   = fmaf(wb.x, h4.x, fmaf(wb.y, h4.y, fmaf(wb.z, h4.z, fmaf(wb.w, h4.w, zb))));
        zbp  = fmaf(wb.x, p4.x, fmaf(wb.y, p4.y, fmaf(wb.z, p4.z, fmaf(wb.w, p4.w, zbp))));
        zbpp = fmaf(wb.x, s4.x, fmaf(wb.y, s4.y, fmaf(wb.z, s4.z, fmaf(wb.w, s4.w, zbpp))));
    }

    float ta = fast_tanh(za), tb = fast_tanh(zb);
    float sa = 1.0f - ta * ta, sb = 1.0f - tb * tb;
    float w3a = sW3[lane], w3b = sW3[lane + 32];
    float va   = fmaf(w3a, ta, w3b * tb);
    float vpa  = fmaf(w3a * sa, zap, w3b * sb * zbp);
    float vppa = fmaf(w3a * sa, zapp - 2.0f * ta * zap * zap,
                      w3b * sb * (zbpp - 2.0f * tb * zbp * zbp));

    #pragma unroll
    for (int off = 16; off; off >>= 1) {
        va   += __shfl_xor_sync(0xffffffffu, va,   off);
        vpa  += __shfl_xor_sync(0xffffffffu, vpa,  off);
        vppa += __shfl_xor_sync(0xffffffffu, vppa, off);
    }
    if (lane == 0) {
        float v    = va + gb3[0];
        float em2t = f3;                             // e^{-2t}
        float g    = vpa * em2t;                     // (dv/dd)/d
        float gp   = (vppa - 2.0f * vpa) * em2t;     // dg/dt
        snode[wrp] = make_float4(v, vpa * HTF, g, gp * HTF);
    }
    __syncthreads();

    // convert 7 intervals to monomial coefficients
    if (tid < 7) {
        int m = base + tid;
        if (m < NT - 1) {
            float4 n0 = snode[tid], n1 = snode[tid + 1];
            float dv = n1.x - n0.x;
            g_coef[2 * m]     = make_float4(n0.x, n0.y,
                                            3.f * dv - 2.f * n0.y - n1.y,
                                            -2.f * dv + n0.y + n1.y);
            float dg = n1.z - n0.z;
            g_coef[2 * m + 1] = make_float4(n0.z, n0.w,
                                            3.f * dg - 2.f * n0.w - n1.w,
                                            -2.f * dg + n0.w + n1.w);
        }
    }
}

// ---------------------------------------------------------------------------
// Forces: one warp per batch, lane = particle. No sqrt, no div, 1 MUFU/pair.
// ---------------------------------------------------------------------------
__global__ void __launch_bounds__(256)
forces_kernel(const float* __restrict__ gpos, float* __restrict__ out, int B)
{
    __shared__ float4 ppos[8][NPART];
    const int lane = threadIdx.x & 31;
    const int wrp  = threadIdx.x >> 5;
    const int b = blockIdx.x * 8 + wrp;
    if (b >= B) return;

    const float px = gpos[b * 96 + lane * 3 + 0];
    const float py = gpos[b * 96 + lane * 3 + 1];
    const float pz = gpos[b * 96 + lane * 3 + 2];
    ppos[wrp][lane] = make_float4(px, py, pz, 0.f);
    __syncwarp();

    const float KL = 0.5f * LN2F * INVHT;   // u = (0.5*ln(d2) - T0) * INVHT
    const float C0 = -T0F * INVHT;
    const float v0 = __ldg(&g_coef[0]).x;   // value at u=0 (self-term to remove)

    float fx = 0.f, fy = 0.f, fz = 0.f, vloc = 0.f;

    #pragma unroll 8
    for (int j = 0; j < NPART; j++) {
        float4 pj = ppos[wrp][j];
        float rx = px - pj.x, ry = py - pj.y, rz = pz - pj.z;
        float d2 = fmaf(rx, rx, fmaf(ry, ry, rz * rz));

        float u = fmaf(__log2f(d2), KL, C0);        // -inf when j==lane -> u=0
        u = fminf(fmaxf(u, 0.0f), (float)NT - 1.001f);
        int   i0 = (int)u;
        float s  = u - (float)i0;

        float4 cv = __ldg(&g_coef[2 * i0]);
        float4 cg = __ldg(&g_coef[2 * i0 + 1]);
        float v = fmaf(fmaf(fmaf(cv.w, s, cv.z), s, cv.y), s, cv.x);
        float g = fmaf(fmaf(fmaf(cg.w, s, cg.z), s, cg.y), s, cg.x);

        g = (d2 > 0.0025f) ? g : 0.0f;   // clipped or self: zero force

        fx = fmaf(-g, rx, fx);
        fy = fmaf(-g, ry, fy);
        fz = fmaf(-g, rz, fz);
        vloc += v;                        // self adds constant v0, removed below
    }
    vloc -= v0;

    out[b * 96 + lane * 3 + 0] = fx;
    out[b * 96 + lane * 3 + 1] = fy;
    out[b * 96 + lane * 3 + 2] = fz;

    #pragma unroll
    for (int off = 16; off; off >>= 1)
        vloc += __shfl_xor_sync(0xffffffffu, vloc, off);
    if (lane == 0)
        out[(long long)B * 96 + b] = 0.5f * vloc;
}

extern "C" void kernel_launch(void* const* d_in, const int* in_sizes, int n_in,
                              void* d_out, int out_size)
{
    const float* pos = (const float*)d_in[0];
    const float* W1  = (const float*)d_in[1];
    const float* b1  = (const float*)d_in[2];
    const float* W2  = (const float*)d_in[3];
    const float* b2  = (const float*)d_in[4];
    const float* W3  = (const float*)d_in[5];
    const float* b3  = (const float*)d_in[6];
    float* out = (float*)d_out;
    const int B = in_sizes[0] / 96;

    build_table<<<(NT + 5) / 7, 256>>>(W1, b1, W2, b2, W3, b3);
    forces_kernel<<<(B + 7) / 8, 256>>>(pos, out, B);
}

// round 8
// speedup vs baseline: 2.5230x; 1.0067x over previous
#include <cuda_runtime.h>
#include <math.h>

#define NPART 32
#define NT    512
#define T0F   (-2.99573227355399099343f)   // logf(0.05)
#define T1F   ( 3.46573590279972654709f)   // logf(32)
#define HTF   ((T1F - T0F) / (float)(NT - 1))
#define INVHT ((float)(NT - 1) / (T1F - T0F))
#define LN2F  (0.69314718055994530942f)

__device__ float4 g_coef[2 * NT];   // interval i: [2i]=value cubic, [2i+1]=force cubic

__device__ __forceinline__ float fast_tanh(float x) {
    float ax = fabsf(x);
    float e  = __expf(ax + ax);
    float t  = 1.0f - __fdividef(2.0f, e + 1.0f);
    return copysignf(t, x);
}

// ---------------------------------------------------------------------------
// Builder: block bn computes nodes 7*bn .. 7*bn+7 (one per warp; one-node
// overlap with next block), converts the 7 interior intervals to monomial
// coefficients in-block. 2nd-order forward AD w.r.t. t = log d.
// ---------------------------------------------------------------------------
__global__ void __launch_bounds__(256)
build_table(const float* __restrict__ gW1, const float* __restrict__ gb1,
            const float* __restrict__ gW2, const float* __restrict__ gb2,
            const float* __restrict__ gW3, const float* __restrict__ gb3)
{
    __shared__ float sW2T[64 * 64];                  // [jj][k]
    __shared__ float sW1[192], sb1[64], sb2[64], sW3[64];
    __shared__ float4 sh[8][16], shp[8][16], shpp[8][16];
    __shared__ float4 snode[8];                      // (v, v'_s, g, g'_s)
    const int tid = threadIdx.x, lane = tid & 31, wrp = tid >> 5;

    for (int idx = tid; idx < 4096; idx += 256) {
        int k = idx >> 6, jj = idx & 63;             // gW2 is [k][jj]
        sW2T[jj * 64 + k] = gW2[idx];
    }
    for (int k = tid; k < 192; k += 256) sW1[k] = gW1[k];
    for (int k = tid; k < 64; k += 256) {
        sb1[k] = gb1[k]; sb2[k] = gb2[k]; sW3[k] = gW3[k];
    }
    __syncthreads();

    const int base = blockIdx.x * 7;
    const int node = min(base + wrp, NT - 1);

    const float t  = T0F + node * HTF;
    const float d  = expf(t);
    const float f1 = d, f2 = 1.0f / d, f3 = f2 * f2;

    // phase A: layer-1 (value, d/dt, d2/dt2); lane fills k=lane, k=lane+32
    float* shs   = (float*)sh[wrp];
    float* shps  = (float*)shp[wrp];
    float* shpps = (float*)shpp[wrp];
    #pragma unroll
    for (int q = 0; q < 2; q++) {
        int k = lane + q * 32;
        float w0 = sW1[k], w1 = sW1[64 + k], w2 = sW1[128 + k];
        float z   = sb1[k] + w0 * f1 + w1 * f2 + w2 * f3;
        float zp  = w0 * f1 - w1 * f2 - 2.0f * w2 * f3;
        float zpp = w0 * f1 + w1 * f2 + 4.0f * w2 * f3;
        float h   = fast_tanh(z);
        float s2  = 1.0f - h * h;
        shs[k]   = h;
        shps[k]  = s2 * zp;
        shpps[k] = s2 * (zpp - 2.0f * h * zp * zp);
    }
    __syncwarp();

    // phase B: lane owns rows jj=lane, lane+32; one pass over k-chunks
    const float4* wra = (const float4*)(&sW2T[lane * 64]);
    const float4* wrb = (const float4*)(&sW2T[(lane + 32) * 64]);
    float za = sb2[lane],      zap = 0.f, zapp = 0.f;
    float zb = sb2[lane + 32], zbp = 0.f, zbpp = 0.f;
    #pragma unroll
    for (int r = 0; r < 16; r++) {
        int rr = (r + lane) & 15;                    // rotate: spread banks
        float4 h4 = sh[wrp][rr];
        float4 p4 = shp[wrp][rr];
        float4 s4 = shpp[wrp][rr];
        float4 wa = wra[rr];
        float4 wb = wrb[rr];
        za   = fmaf(wa.x, h4.x, fmaf(wa.y, h4.y, fmaf(wa.z, h4.z, fmaf(wa.w, h4.w, za))));
        zap  = fmaf(wa.x, p4.x, fmaf(wa.y, p4.y, fmaf(wa.z, p4.z, fmaf(wa.w, p4.w, zap))));
        zapp = fmaf(wa.x, s4.x, fmaf(wa.y, s4.y, fmaf(wa.z, s4.z, fmaf(wa.w, s4.w, zapp))));
        zb   = fmaf(wb.x, h4.x, fmaf(wb.y, h4.y, fmaf(wb.z, h4.z, fmaf(wb.w, h4.w, zb))));
        zbp  = fmaf(wb.x, p4.x, fmaf(wb.y, p4.y, fmaf(wb.z, p4.z, fmaf(wb.w, p4.w, zbp))));
        zbpp = fmaf(wb.x, s4.x, fmaf(wb.y, s4.y, fmaf(wb.z, s4.z, fmaf(wb.w, s4.w, zbpp))));
    }

    float ta = fast_tanh(za), tb = fast_tanh(zb);
    float sa = 1.0f - ta * ta, sb = 1.0f - tb * tb;
    float w3a = sW3[lane], w3b = sW3[lane + 32];
    float va   = fmaf(w3a, ta, w3b * tb);
    float vpa  = fmaf(w3a * sa, zap, w3b * sb * zbp);
    float vppa = fmaf(w3a * sa, zapp - 2.0f * ta * zap * zap,
                      w3b * sb * (zbpp - 2.0f * tb * zbp * zbp));

    #pragma unroll
    for (int off = 16; off; off >>= 1) {
        va   += __shfl_xor_sync(0xffffffffu, va,   off);
        vpa  += __shfl_xor_sync(0xffffffffu, vpa,  off);
        vppa += __shfl_xor_sync(0xffffffffu, vppa, off);
    }
    if (lane == 0) {
        float v    = va + gb3[0];
        float em2t = f3;                             // e^{-2t}
        float g    = vpa * em2t;                     // (dv/dd)/d
        float gp   = (vppa - 2.0f * vpa) * em2t;     // dg/dt
        snode[wrp] = make_float4(v, vpa * HTF, g, gp * HTF);
    }
    __syncthreads();

    if (tid < 7) {
        int m = base + tid;
        if (m < NT - 1) {
            float4 n0 = snode[tid], n1 = snode[tid + 1];
            float dv = n1.x - n0.x;
            g_coef[2 * m]     = make_float4(n0.x, n0.y,
                                            3.f * dv - 2.f * n0.y - n1.y,
                                            -2.f * dv + n0.y + n1.y);
            float dg = n1.z - n0.z;
            g_coef[2 * m + 1] = make_float4(n0.z, n0.w,
                                            3.f * dg - 2.f * n0.w - n1.w,
                                            -2.f * dg + n0.w + n1.w);
        }
    }
}

// ---------------------------------------------------------------------------
// Forces: one warp per batch, lane = particle. Table staged in smem so the
// data-dependent gathers hit the LDS crossbar, not the L1TEX queue.
// ---------------------------------------------------------------------------
__global__ void __launch_bounds__(256)
forces_kernel(const float* __restrict__ gpos, float* __restrict__ out, int B)
{
    __shared__ float4 scoef[2 * NT];    // 16 KB
    __shared__ float4 ppos[8][NPART];
    const int tid  = threadIdx.x;
    const int lane = tid & 31;
    const int wrp  = tid >> 5;
    const int b = blockIdx.x * 8 + wrp;

    #pragma unroll
    for (int q = 0; q < (2 * NT) / 256; q++)
        scoef[q * 256 + tid] = __ldg(&g_coef[q * 256 + tid]);

    float px = 0.f, py = 0.f, pz = 0.f;
    if (b < B) {
        px = gpos[b * 96 + lane * 3 + 0];
        py = gpos[b * 96 + lane * 3 + 1];
        pz = gpos[b * 96 + lane * 3 + 2];
        ppos[wrp][lane] = make_float4(px, py, pz, 0.f);
    }
    __syncthreads();
    if (b >= B) return;

    const float KL = 0.5f * LN2F * INVHT;   // u = (0.5*ln(d2) - T0) * INVHT
    const float C0 = -T0F * INVHT;
    const float v0 = scoef[0].x;            // value at u=0 (self-term)

    float fx = 0.f, fy = 0.f, fz = 0.f, vloc = 0.f;

    #pragma unroll 8
    for (int j = 0; j < NPART; j++) {
        float4 pj = ppos[wrp][j];
        float rx = px - pj.x, ry = py - pj.y, rz = pz - pj.z;
        float d2 = fmaf(rx, rx, fmaf(ry, ry, rz * rz));

        float u = fmaf(__log2f(d2), KL, C0);        // -inf when j==lane -> u=0
        u = fminf(fmaxf(u, 0.0f), (float)NT - 1.001f);
        int   i0 = (int)u;
        float s  = u - (float)i0;

        float4 cv = scoef[2 * i0];
        float4 cg = scoef[2 * i0 + 1];
        float v = fmaf(fmaf(fmaf(cv.w, s, cv.z), s, cv.y), s, cv.x);
        float g = fmaf(fmaf(fmaf(cg.w, s, cg.z), s, cg.y), s, cg.x);

        g = (d2 > 0.0025f) ? g : 0.0f;   // clipped or self: zero force

        fx = fmaf(-g, rx, fx);
        fy = fmaf(-g, ry, fy);
        fz = fmaf(-g, rz, fz);
        vloc += v;                        // self adds constant v0, removed below
    }
    vloc -= v0;

    out[b * 96 + lane * 3 + 0] = fx;
    out[b * 96 + lane * 3 + 1] = fy;
    out[b * 96 + lane * 3 + 2] = fz;

    #pragma unroll
    for (int off = 16; off; off >>= 1)
        vloc += __shfl_xor_sync(0xffffffffu, vloc, off);
    if (lane == 0)
        out[(long long)B * 96 + b] = 0.5f * vloc;
}

extern "C" void kernel_launch(void* const* d_in, const int* in_sizes, int n_in,
                              void* d_out, int out_size)
{
    const float* pos = (const float*)d_in[0];
    const float* W1  = (const float*)d_in[1];
    const float* b1  = (const float*)d_in[2];
    const float* W2  = (const float*)d_in[3];
    const float* b2  = (const float*)d_in[4];
    const float* W3  = (const float*)d_in[5];
    const float* b3  = (const float*)d_in[6];
    float* out = (float*)d_out;
    const int B = in_sizes[0] / 96;

    build_table<<<(NT + 5) / 7, 256>>>(W1, b1, W2, b2, W3, b3);
    forces_kernel<<<(B + 7) / 8, 256>>>(pos, out, B);
}

// round 9
// speedup vs baseline: 3.4240x; 1.3571x over previous
#include <cuda_runtime.h>
#include <math.h>

#define NPART 32
#define NT    256
#define T0F   (-2.99573227355399099343f)   // logf(0.05)
#define T1F   ( 3.46573590279972654709f)   // logf(32)
#define HTF   ((T1F - T0F) / (float)(NT - 1))
#define INVHT ((float)(NT - 1) / (T1F - T0F))
#define LN2F  (0.69314718055994530942f)
#define FULLM 0xffffffffu

__device__ float4 g_coef[2 * NT];   // interval i: [2i]=value cubic, [2i+1]=force cubic

__device__ __forceinline__ float fast_tanh(float x) {
    float ax = fabsf(x);
    float e  = __expf(ax + ax);
    float t  = 1.0f - __fdividef(2.0f, e + 1.0f);
    return copysignf(t, x);
}

// ---------------------------------------------------------------------------
// Builder: block bn computes nodes 7*bn .. 7*bn+7 (one per warp; one-node
// overlap with next block), converts 7 intervals to monomial coefficients.
// 2nd-order forward AD w.r.t. t = log d.
// ---------------------------------------------------------------------------
__global__ void __launch_bounds__(256)
build_table(const float* __restrict__ gW1, const float* __restrict__ gb1,
            const float* __restrict__ gW2, const float* __restrict__ gb2,
            const float* __restrict__ gW3, const float* __restrict__ gb3)
{
    __shared__ float sW2T[64 * 64];                  // [jj][k]
    __shared__ float sW1[192], sb1[64], sb2[64], sW3[64];
    __shared__ float4 sh[8][16], shp[8][16], shpp[8][16];
    __shared__ float4 snode[8];                      // (v, v'_s, g, g'_s)
    const int tid = threadIdx.x, lane = tid & 31, wrp = tid >> 5;

    for (int idx = tid; idx < 4096; idx += 256) {
        int k = idx >> 6, jj = idx & 63;             // gW2 is [k][jj]
        sW2T[jj * 64 + k] = gW2[idx];
    }
    for (int k = tid; k < 192; k += 256) sW1[k] = gW1[k];
    for (int k = tid; k < 64; k += 256) {
        sb1[k] = gb1[k]; sb2[k] = gb2[k]; sW3[k] = gW3[k];
    }
    __syncthreads();

    const int base = blockIdx.x * 7;
    const int node = min(base + wrp, NT - 1);

    const float t  = T0F + node * HTF;
    const float d  = expf(t);
    const float f1 = d, f2 = 1.0f / d, f3 = f2 * f2;

    float* shs   = (float*)sh[wrp];
    float* shps  = (float*)shp[wrp];
    float* shpps = (float*)shpp[wrp];
    #pragma unroll
    for (int q = 0; q < 2; q++) {
        int k = lane + q * 32;
        float w0 = sW1[k], w1 = sW1[64 + k], w2 = sW1[128 + k];
        float z   = sb1[k] + w0 * f1 + w1 * f2 + w2 * f3;
        float zp  = w0 * f1 - w1 * f2 - 2.0f * w2 * f3;
        float zpp = w0 * f1 + w1 * f2 + 4.0f * w2 * f3;
        float h   = fast_tanh(z);
        float s2  = 1.0f - h * h;
        shs[k]   = h;
        shps[k]  = s2 * zp;
        shpps[k] = s2 * (zpp - 2.0f * h * zp * zp);
    }
    __syncwarp();

    const float4* wra = (const float4*)(&sW2T[lane * 64]);
    const float4* wrb = (const float4*)(&sW2T[(lane + 32) * 64]);
    float za = sb2[lane],      zap = 0.f, zapp = 0.f;
    float zb = sb2[lane + 32], zbp = 0.f, zbpp = 0.f;
    #pragma unroll
    for (int r = 0; r < 16; r++) {
        int rr = (r + lane) & 15;
        float4 h4 = sh[wrp][rr];
        float4 p4 = shp[wrp][rr];
        float4 s4 = shpp[wrp][rr];
        float4 wa = wra[rr];
        float4 wb = wrb[rr];
        za   = fmaf(wa.x, h4.x, fmaf(wa.y, h4.y, fmaf(wa.z, h4.z, fmaf(wa.w, h4.w, za))));
        zap  = fmaf(wa.x, p4.x, fmaf(wa.y, p4.y, fmaf(wa.z, p4.z, fmaf(wa.w, p4.w, zap))));
        zapp = fmaf(wa.x, s4.x, fmaf(wa.y, s4.y, fmaf(wa.z, s4.z, fmaf(wa.w, s4.w, zapp))));
        zb   = fmaf(wb.x, h4.x, fmaf(wb.y, h4.y, fmaf(wb.z, h4.z, fmaf(wb.w, h4.w, zb))));
        zbp  = fmaf(wb.x, p4.x, fmaf(wb.y, p4.y, fmaf(wb.z, p4.z, fmaf(wb.w, p4.w, zbp))));
        zbpp = fmaf(wb.x, s4.x, fmaf(wb.y, s4.y, fmaf(wb.z, s4.z, fmaf(wb.w, s4.w, zbpp))));
    }

    float ta = fast_tanh(za), tb = fast_tanh(zb);
    float sa = 1.0f - ta * ta, sb = 1.0f - tb * tb;
    float w3a = sW3[lane], w3b = sW3[lane + 32];
    float va   = fmaf(w3a, ta, w3b * tb);
    float vpa  = fmaf(w3a * sa, zap, w3b * sb * zbp);
    float vppa = fmaf(w3a * sa, zapp - 2.0f * ta * zap * zap,
                      w3b * sb * (zbpp - 2.0f * tb * zbp * zbp));

    #pragma unroll
    for (int off = 16; off; off >>= 1) {
        va   += __shfl_xor_sync(FULLM, va,   off);
        vpa  += __shfl_xor_sync(FULLM, vpa,  off);
        vppa += __shfl_xor_sync(FULLM, vppa, off);
    }
    if (lane == 0) {
        float v    = va + gb3[0];
        float em2t = f3;                             // e^{-2t}
        float g    = vpa * em2t;                     // (dv/dd)/d
        float gp   = (vppa - 2.0f * vpa) * em2t;     // dg/dt
        snode[wrp] = make_float4(v, vpa * HTF, g, gp * HTF);
    }
    __syncthreads();

    if (tid < 7) {
        int m = base + tid;
        if (m < NT - 1) {
            float4 n0 = snode[tid], n1 = snode[tid + 1];
            float dv = n1.x - n0.x;
            g_coef[2 * m]     = make_float4(n0.x, n0.y,
                                            3.f * dv - 2.f * n0.y - n1.y,
                                            -2.f * dv + n0.y + n1.y);
            float dg = n1.z - n0.z;
            g_coef[2 * m + 1] = make_float4(n0.z, n0.w,
                                            3.f * dg - 2.f * n0.w - n1.w,
                                            -2.f * dg + n0.w + n1.w);
        }
    }
}

// ---------------------------------------------------------------------------
// Forces: 2 warps per batch (k=1..8 / 9..16); lane l evaluates pair (l, l+k)
// once and delivers the reaction force to lane l+k via shuffle.
// ---------------------------------------------------------------------------
__global__ void __launch_bounds__(256)
forces_kernel(const float* __restrict__ gpos, float* __restrict__ out, int B)
{
    __shared__ float4 scoef[2 * NT];   // 8 KB
    __shared__ float4 sF[8][NPART];    // per-warp partial forces
    __shared__ float  sV[8];
    const int tid  = threadIdx.x;
    const int lane = tid & 31;
    const int wrp  = tid >> 5;
    const int bq   = blockIdx.x * 4 + (wrp >> 1);   // batch of this warp
    const int half = wrp & 1;                       // 0: k=1..8, 1: k=9..16

    #pragma unroll
    for (int q = 0; q < (2 * NT) / 256; q++)
        scoef[q * 256 + tid] = __ldg(&g_coef[q * 256 + tid]);

    float px = 0.f, py = 0.f, pz = 0.f;
    if (bq < B) {
        px = gpos[bq * 96 + lane * 3 + 0];
        py = gpos[bq * 96 + lane * 3 + 1];
        pz = gpos[bq * 96 + lane * 3 + 2];
    }
    __syncthreads();

    const float KL = 0.5f * LN2F * INVHT;   // u = (0.5*ln(d2) - T0) * INVHT
    const float C0 = -T0F * INVHT;

    float fx = 0.f, fy = 0.f, fz = 0.f, vloc = 0.f;
    const int k0 = 1 + half * 8;

    #pragma unroll
    for (int kk = 0; kk < 8; kk++) {
        const int k = k0 + kk;
        const int src = (lane + k) & 31;
        float qx = __shfl_sync(FULLM, px, src);
        float qy = __shfl_sync(FULLM, py, src);
        float qz = __shfl_sync(FULLM, pz, src);
        float rx = px - qx, ry = py - qy, rz = pz - qz;
        float d2 = fmaf(rx, rx, fmaf(ry, ry, rz * rz));

        float u = fmaf(__log2f(d2), KL, C0);
        u = fminf(fmaxf(u, 0.0f), (float)NT - 1.001f);
        int   i0 = (int)u;
        float s  = u - (float)i0;

        float4 cv = scoef[2 * i0];
        float4 cg = scoef[2 * i0 + 1];
        float v = fmaf(fmaf(fmaf(cv.w, s, cv.z), s, cv.y), s, cv.x);
        float g = fmaf(fmaf(fmaf(cg.w, s, cg.z), s, cg.y), s, cg.x);

        g = (d2 > 0.0025f) ? g : 0.0f;   // clipped: zero force

        float cx = g * rx, cy = g * ry, cz = g * rz;
        fx -= cx; fy -= cy; fz -= cz;     // own side: F_l += -g*r

        if (k != 16) {
            // reaction: F_{l+k} += +g*r ; lane m pulls from lane m-k
            const int from = (lane - k) & 31;
            fx += __shfl_sync(FULLM, cx, from);
            fy += __shfl_sync(FULLM, cy, from);
            fz += __shfl_sync(FULLM, cz, from);
            vloc += v;
        } else {
            vloc += 0.5f * v;             // pair (l, l+16) computed by 2 lanes
        }
    }

    sF[wrp][lane] = make_float4(fx, fy, fz, 0.f);
    #pragma unroll
    for (int off = 16; off; off >>= 1)
        vloc += __shfl_xor_sync(FULLM, vloc, off);
    if (lane == 0) sV[wrp] = vloc;
    __syncthreads();

    if (half == 0 && bq < B) {
        float4 a = sF[wrp][lane];
        float4 c = sF[wrp + 1][lane];
        out[bq * 96 + lane * 3 + 0] = a.x + c.x;
        out[bq * 96 + lane * 3 + 1] = a.y + c.y;
        out[bq * 96 + lane * 3 + 2] = a.z + c.z;
        if (lane == 0)
            out[(long long)B * 96 + bq] = sV[wrp] + sV[wrp + 1];
    }
}

extern "C" void kernel_launch(void* const* d_in, const int* in_sizes, int n_in,
                              void* d_out, int out_size)
{
    const float* pos = (const float*)d_in[0];
    const float* W1  = (const float*)d_in[1];
    const float* b1  = (const float*)d_in[2];
    const float* W2  = (const float*)d_in[3];
    const float* b2  = (const float*)d_in[4];
    const float* W3  = (const float*)d_in[5];
    const float* b3  = (const float*)d_in[6];
    float* out = (float*)d_out;
    const int B = in_sizes[0] / 96;

    build_table<<<(NT + 5) / 7, 256>>>(W1, b1, W2, b2, W3, b3);
    forces_kernel<<<(B + 3) / 4, 256>>>(pos, out, B);
}